// round 8
// baseline (speedup 1.0000x reference)
#include <cuda_runtime.h>
#include <cuda_bf16.h>

// Problem constants (fixed by the reference)
#define BQ    2
#define NPTS  8192
#define GQ    256
#define XMINF (-35.0f)
#define CELLW (0.2734375f)   // 70/256, exactly representable

// Spatial bucket grid for exact 1-NN
#define GS      16
#define GS3     (GS * GS * GS)
#define CELLSZ  4.25f          // 68/16, exact in fp32
#define INVCELL (1.0f / 4.25f)

// -------- scratch (device globals; zero-initialized at load; every kernel
// restores what it consumed, so graph replays see identical entry state) ----
__device__ int    g_ccnt  [2 * BQ * GS3];          // per-cell counts (re-zeroed by scan)
__device__ int    g_offs  [2 * BQ * (GS3 + 1)];    // exclusive offsets + sentinel
__device__ int    g_cursor[2 * BQ * GS3];          // scatter cursors
__device__ int    g_cellid[2 * BQ * NPTS];         // cell id per point
__device__ float4 g_sorted[2 * BQ * NPTS];         // bucketed (x,y,z,orig_idx)
__device__ unsigned long long g_best_x[BQ * NPTS]; // (dist_bits<<32)|argmin_j
__device__ unsigned long long g_best_y[BQ * NPTS]; // (dist_bits<<32)|argmin_i
__device__ int    g_grid[BQ * GQ * GQ];            // ((n+1)<<1)|label, 0 = empty (re-zeroed by loss)
__device__ int    g_oflow [2 * BQ * NPTS];         // tier-2 query list
__device__ int    g_oflow2[2 * BQ * NPTS];         // tier-3 query list
__device__ int    g_ocount, g_ocount2;             // list sizes (re-zeroed by epilogue)
__device__ double g_sum;
__device__ int    g_vcnt;
__device__ unsigned g_done;

__device__ __forceinline__ int cell_coord(float v) {
    int c = (int)((v + 34.0f) * INVCELL);
    return min(max(c, 0), GS - 1);
}

// ===== histogram =====
__global__ void hist_kernel(const float* __restrict__ p_i,
                            const float* __restrict__ p_j) {
    int t = blockIdx.x * blockDim.x + threadIdx.x;   // [src][b][n]
    int n = t & (NPTS - 1), b = (t >> 13) & 1, src = t >> 14;
    const float* P = (src ? p_j : p_i) + ((size_t)b * NPTS + n) * 3;
    int cell = (cell_coord(P[2]) * GS + cell_coord(P[1])) * GS + cell_coord(P[0]);
    g_cellid[t] = cell;
    atomicAdd(&g_ccnt[(src * BQ + b) * GS3 + cell], 1);
}

// ===== exclusive scan per combo; offs+sentinel, cursors; re-zero counts =====
__global__ void scan_kernel() {
    const int combo = blockIdx.x;
    const int base  = combo * GS3;
    const int obase = combo * (GS3 + 1);
    const int lane = threadIdx.x & 31, warp = threadIdx.x >> 5;
    __shared__ int wsum[16];

    int v[8]; int s = 0;
    #pragma unroll
    for (int k = 0; k < 8; k++) { v[k] = g_ccnt[base + threadIdx.x * 8 + k]; s += v[k]; }

    int inc = s;
    #pragma unroll
    for (int o = 1; o < 32; o <<= 1) {
        int x = __shfl_up_sync(0xFFFFFFFFu, inc, o);
        if (lane >= o) inc += x;
    }
    if (lane == 31) wsum[warp] = inc;
    __syncthreads();
    if (warp == 0 && lane < 16) {
        int w = wsum[lane];
        #pragma unroll
        for (int o = 1; o < 16; o <<= 1) {
            int x = __shfl_up_sync(0xFFFFu, w, o);
            if (lane >= o) w += x;
        }
        wsum[lane] = w;
    }
    __syncthreads();
    int excl = inc - s + (warp ? wsum[warp - 1] : 0);
    #pragma unroll
    for (int k = 0; k < 8; k++) {
        int idx = threadIdx.x * 8 + k;
        g_offs[obase + idx] = excl;
        g_cursor[base + idx] = excl;
        g_ccnt[base + idx] = 0;          // restore for next replay
        excl += v[k];
    }
    if (threadIdx.x == 0) g_offs[obase + GS3] = NPTS;
}

// ===== scatter points into bucket order =====
__global__ void scatter_kernel(const float* __restrict__ p_i,
                               const float* __restrict__ p_j) {
    int t = blockIdx.x * blockDim.x + threadIdx.x;
    int n = t & (NPTS - 1), b = (t >> 13) & 1, src = t >> 14;
    const float* P = (src ? p_j : p_i) + ((size_t)b * NPTS + n) * 3;
    int cell = g_cellid[t];
    int pos = atomicAdd(&g_cursor[(src * BQ + b) * GS3 + cell], 1);
    g_sorted[(src * BQ + b) * NPTS + pos] = make_float4(P[0], P[1], P[2], __int_as_float(n));
}

__device__ __forceinline__ void eval_range(const float4* __restrict__ T,
                                           int p0, int p1,
                                           float qx, float qy, float qz,
                                           unsigned long long& bestkey) {
    #pragma unroll 2
    for (int p = p0; p < p1; p++) {
        float4 tp = T[p];
        // same fp32 op order as the reference: (|dx|+|dy|)+|dz|
        float d = fabsf(qx - tp.x) + fabsf(qy - tp.y);
        d += fabsf(qz - tp.z);
        unsigned long long key =
            ((unsigned long long)__float_as_uint(d) << 32) |
            (unsigned)__float_as_int(tp.w);
        if (key < bestkey) bestkey = key;
    }
}

// ===== tier 1: 3x3x3 cell box, 2 lanes/query (measured 13.3us) =====
// Rows split by parity across the lane pair; row x-runs are contiguous offs
// ranges, all prefetched up-front. Packed (dist_bits<<32)|orig key-min = exact
// min dist, min-index tie-break (jnp.argmin). If best could still lose to a
// Chebyshev>=2 candidate (L1 lower bound CELLSZ), push query to tier 2.
__global__ void query_kernel() {
    int t = blockIdx.x * blockDim.x + threadIdx.x;
    const int sub = t & 1;
    int g = t >> 1;                                  // [dir][b][q]
    int q = g & (NPTS - 1), b = (g >> 13) & 1, dir = g >> 14;
    int qc = dir * BQ + b;
    int tc = (1 - dir) * BQ + b;
    const unsigned gmask = 0x3u << (threadIdx.x & 30);

    float4 Q = g_sorted[qc * NPTS + q];
    const float qx = Q.x, qy = Q.y, qz = Q.z;
    const int orig = __float_as_int(Q.w);

    const int* __restrict__ offs = &g_offs[tc * (GS3 + 1)];
    const float4* __restrict__ T = &g_sorted[tc * NPTS];

    const int qcx = cell_coord(qx), qcy = cell_coord(qy), qcz = cell_coord(qz);
    const int x0 = max(qcx - 1, 0), x1 = min(qcx + 1, GS - 1);

    int P0[9], P1[9];
    #pragma unroll
    for (int k = 0; k < 9; k++) {
        int dz = k / 3 - 1, dy = k - (k / 3) * 3 - 1;
        int cz = qcz + dz, cy = qcy + dy;
        bool mine = ((k & 1) == sub) & (cz >= 0) & (cz < GS) & (cy >= 0) & (cy < GS);
        int rowbase = (cz * GS + cy) * GS;
        P0[k] = mine ? __ldg(&offs[rowbase + x0])     : 0;
        P1[k] = mine ? __ldg(&offs[rowbase + x1 + 1]) : 0;
    }

    unsigned long long bestkey = ((unsigned long long)0x7F800000u << 32); // +inf
    #pragma unroll
    for (int k = 0; k < 9; k++)
        eval_range(T, P0[k], P1[k], qx, qy, qz, bestkey);

    {
        unsigned long long other = __shfl_xor_sync(gmask, bestkey, 1);
        if (other < bestkey) bestkey = other;
    }

    if (sub == 0) {
        (dir ? g_best_y : g_best_x)[b * NPTS + orig] = bestkey;
        float bestd = __uint_as_float((unsigned)(bestkey >> 32));
        if (!(CELLSZ - 1e-3f > bestd)) {
            int e = atomicAdd(&g_ocount, 1);
            g_oflow[e] = g;
        }
    }
}

// ===== tier 2: ONE query per warp, full 7x7x7 box (Chebyshev<=3) =====
// 49 row-contiguous ranges RR'd over 32 lanes; warp-uniform control flow,
// full-warp shfl reduce. Redundantly re-covers the 3x3x3 box (key-min is
// idempotent). Afterwards any uncovered candidate is at Chebyshev>=4 ==>
// L1 >= 3*CELLSZ; if best could still lose to that, push to tier 3 (~never).
__global__ void oflow2_kernel() {
    const int wg   = (blockIdx.x * blockDim.x + threadIdx.x) >> 5;
    const int lane = threadIdx.x & 31;
    if (wg >= g_ocount) return;                     // warp-uniform exit

    int g = g_oflow[wg];
    int q = g & (NPTS - 1), b = (g >> 13) & 1, dir = g >> 14;
    int qc = dir * BQ + b, tc = (1 - dir) * BQ + b;

    float4 Q = g_sorted[qc * NPTS + q];
    const float qx = Q.x, qy = Q.y, qz = Q.z;
    const int orig = __float_as_int(Q.w);

    const int* __restrict__ offs = &g_offs[tc * (GS3 + 1)];
    const float4* __restrict__ T = &g_sorted[tc * NPTS];

    const int qcx = cell_coord(qx), qcy = cell_coord(qy), qcz = cell_coord(qz);
    const int x0 = max(qcx - 3, 0), x1 = min(qcx + 3, GS - 1);
    const int z0 = max(qcz - 3, 0), z1 = min(qcz + 3, GS - 1);
    const int y0 = max(qcy - 3, 0), y1 = min(qcy + 3, GS - 1);

    unsigned long long bestkey = (dir ? g_best_y : g_best_x)[b * NPTS + orig];

    int k = 0;
    for (int cz = z0; cz <= z1; cz++) {
        for (int cy = y0; cy <= y1; cy++) {
            if ((k++ & 31) != lane) continue;
            int rowbase = (cz * GS + cy) * GS;
            eval_range(T, offs[rowbase + x0], offs[rowbase + x1 + 1],
                       qx, qy, qz, bestkey);
        }
    }
    #pragma unroll
    for (int o = 1; o <= 16; o <<= 1) {
        unsigned long long other = __shfl_xor_sync(0xFFFFFFFFu, bestkey, o);
        if (other < bestkey) bestkey = other;
    }

    if (lane == 0) {
        (dir ? g_best_y : g_best_x)[b * NPTS + orig] = bestkey;
        float bestd = __uint_as_float((unsigned)(bestkey >> 32));
        if (!(3.0f * CELLSZ - 1e-3f > bestd)) {
            int e = atomicAdd(&g_ocount2, 1);
            g_oflow2[e] = g;
        }
    }
}

// ===== tier 3 (essentially never): expanding rings r>=4, one query/warp =====
__global__ void oflow3_kernel() {
    const int wg   = (blockIdx.x * blockDim.x + threadIdx.x) >> 5;
    const int lane = threadIdx.x & 31;
    if (wg >= g_ocount2) return;

    int g = g_oflow2[wg];
    int q = g & (NPTS - 1), b = (g >> 13) & 1, dir = g >> 14;
    int qc = dir * BQ + b, tc = (1 - dir) * BQ + b;

    float4 Q = g_sorted[qc * NPTS + q];
    const float qx = Q.x, qy = Q.y, qz = Q.z;
    const int orig = __float_as_int(Q.w);

    const int* __restrict__ offs = &g_offs[tc * (GS3 + 1)];
    const float4* __restrict__ T = &g_sorted[tc * NPTS];

    const int qcx = cell_coord(qx), qcy = cell_coord(qy), qcz = cell_coord(qz);

    unsigned long long bestkey = (dir ? g_best_y : g_best_x)[b * NPTS + orig];

    for (int r = 4; r < GS; r++) {
        float bestd = __uint_as_float((unsigned)(bestkey >> 32));
        if ((float)(r - 1) * CELLSZ - 1e-3f > bestd) break;

        int z0 = max(qcz - r, 0), z1 = min(qcz + r, GS - 1);
        int y0 = max(qcy - r, 0), y1 = min(qcy + r, GS - 1);
        int x0 = max(qcx - r, 0), x1 = min(qcx + r, GS - 1);
        int k = 0;
        for (int cz = z0; cz <= z1; cz++) {
            int az = abs(cz - qcz);
            for (int cy = y0; cy <= y1; cy++) {
                if ((k++ & 31) != lane) continue;
                int am = max(az, abs(cy - qcy));
                int rowbase = (cz * GS + cy) * GS;
                if (am == r) {
                    eval_range(T, offs[rowbase + x0], offs[rowbase + x1 + 1],
                               qx, qy, qz, bestkey);
                } else {
                    #pragma unroll
                    for (int sgn = 0; sgn < 2; sgn++) {
                        int cx = sgn ? qcx + r : qcx - r;
                        if (cx < 0 || cx > GS - 1) continue;
                        int c = rowbase + cx;
                        eval_range(T, offs[c], offs[c + 1], qx, qy, qz, bestkey);
                    }
                }
            }
        }
        #pragma unroll
        for (int o = 1; o <= 16; o <<= 1) {
            unsigned long long other = __shfl_xor_sync(0xFFFFFFFFu, bestkey, o);
            if (other < bestkey) bestkey = other;
        }
    }

    if (lane == 0)
        (dir ? g_best_y : g_best_x)[b * NPTS + orig] = bestkey;
}

// ===== epilogue: classify, gather p_j, scatter label into grid =====
__global__ void epilogue_kernel(const float* __restrict__ pj,
                                const float* __restrict__ flow_err,
                                const int*  __restrict__ nf) {
    int t = blockIdx.x * blockDim.x + threadIdx.x; // = b*NPTS + n
    int b = t >> 13;
    int n = t & (NPTS - 1);
    if (t == 0) { g_ocount = 0; g_ocount2 = 0; }   // restore for next replay

    float fe = __ldg(&flow_err[t]);
    int   nfv = __ldg(&nf[t]);
    unsigned long long kx = g_best_x[t];
    unsigned long long ky = g_best_y[t];

    float chx = __uint_as_float((unsigned)(kx >> 32));
    float chy = __uint_as_float((unsigned)(ky >> 32));
    int   jr  = (int)(kx & 0xFFFFFFFFu);

    float rigid = (chx + chy) * 0.5f;          // same op order as reference
    bool  dyn   = fe > rigid;
    int   idx   = dyn ? nfv : jr;
    int   label = dyn ? 1 : 0;

    const float* P = pj + ((size_t)b * NPTS + idx) * 3;
    float px = P[0], py = P[1];

    // IEEE fp32 divide to match XLA exactly (immune to --use_fast_math)
    int gx = (int)__fdiv_rn(px - XMINF, CELLW);
    int gy = (int)__fdiv_rn(py - XMINF, CELLW);
    gx = min(max(gx, 0), GQ - 1);
    gy = min(max(gy, 0), GQ - 1);

    atomicMax(&g_grid[(b * GQ + gx) * GQ + gy], ((n + 1) << 1) | label);
}

// ===== masked cross-entropy + fused finalize (last-block pattern) =====
__global__ void loss_kernel(const float* __restrict__ mos, float* __restrict__ out) {
    int t = blockIdx.x * blockDim.x + threadIdx.x;
    float s = 0.0f;
    int   c = 0;
    {
        int v = g_grid[t];
        if (v > 0) {
            g_grid[t] = 0;                       // restore for next replay
            int label = v & 1;
            int b     = t >> 16;
            int cell  = t & (GQ * GQ - 1);
            const float* Mb = mos + (size_t)b * 2 * GQ * GQ;
            float m0 = Mb[cell];
            float m1 = Mb[GQ * GQ + cell];
            float lse = fmaxf(m0, m1) + log1pf(__expf(-fabsf(m0 - m1)));
            s = lse - (label ? m1 : m0);
            c = 1;
        }
    }
    #pragma unroll
    for (int o = 16; o > 0; o >>= 1) {
        s += __shfl_down_sync(0xFFFFFFFFu, s, o);
        c += __shfl_down_sync(0xFFFFFFFFu, c, o);
    }
    __shared__ float ss[8];
    __shared__ int   sc[8];
    __shared__ bool  sLast;
    int lane = threadIdx.x & 31, warp = threadIdx.x >> 5;
    if (lane == 0) { ss[warp] = s; sc[warp] = c; }
    __syncthreads();
    if (warp == 0) {
        s = (lane < 8) ? ss[lane] : 0.0f;
        c = (lane < 8) ? sc[lane] : 0;
        #pragma unroll
        for (int o = 4; o > 0; o >>= 1) {
            s += __shfl_down_sync(0xFFFFFFFFu, s, o);
            c += __shfl_down_sync(0xFFFFFFFFu, c, o);
        }
        if (lane == 0) {
            if (s != 0.0f) atomicAdd(&g_sum, (double)s);
            if (c)         atomicAdd(&g_vcnt, c);
            __threadfence();
            unsigned d = atomicAdd(&g_done, 1u);
            sLast = (d == gridDim.x - 1);
        }
    }
    __syncthreads();
    if (sLast && threadIdx.x == 0) {
        int cnt = g_vcnt;
        if (cnt < 1) cnt = 1;
        out[0] = (float)(g_sum / (double)cnt);
        g_sum = 0.0; g_vcnt = 0; g_done = 0;
    }
}

// -------- launch: 8 graph nodes --------
extern "C" void kernel_launch(void* const* d_in, const int* in_sizes, int n_in,
                              void* d_out, int out_size) {
    const float* p_i  = (const float*)d_in[0]; // (B,N,3)
    const float* mos  = (const float*)d_in[1]; // (B,2,G,G)
    const float* p_j  = (const float*)d_in[2]; // (B,M,3)
    const float* ferr = (const float*)d_in[3]; // (B,N)
    const int*   nf   = (const int*)d_in[4];   // (B,N,1)
    float* out = (float*)d_out;

    hist_kernel<<<(2 * BQ * NPTS) / 256, 256>>>(p_i, p_j);
    scan_kernel<<<2 * BQ, 512>>>();
    scatter_kernel<<<(2 * BQ * NPTS) / 256, 256>>>(p_i, p_j);
    query_kernel<<<(2 * BQ * NPTS * 2) / 256, 256>>>();
    oflow2_kernel<<<(2 * BQ * NPTS * 32) / 256, 256>>>();  // worst case; early-exit
    oflow3_kernel<<<(2 * BQ * NPTS * 32) / 256, 256>>>();  // worst case; early-exit
    epilogue_kernel<<<(BQ * NPTS) / 256, 256>>>(p_j, ferr, nf);
    loss_kernel<<<(BQ * GQ * GQ) / 256, 256>>>(mos, out);
}

// round 9
// speedup vs baseline: 3.9406x; 3.9406x over previous
#include <cuda_runtime.h>
#include <cuda_bf16.h>

// Problem constants (fixed by the reference)
#define BQ    2
#define NPTS  8192
#define GQ    256
#define XMINF (-35.0f)
#define CELLW (0.2734375f)   // 70/256, exactly representable

// Spatial bucket grid for exact 1-NN
#define GS      16
#define GS3     (GS * GS * GS)
#define CELLSZ  4.25f          // 68/16, exact in fp32
#define INVCELL (1.0f / 4.25f)

// -------- scratch (device globals; zero-initialized at load; every kernel
// restores what it consumed, so graph replays see identical entry state) ----
__device__ int    g_ccnt  [2 * BQ * GS3];          // per-cell counts (re-zeroed by scan)
__device__ int    g_offs  [2 * BQ * (GS3 + 1)];    // exclusive offsets + sentinel
__device__ int    g_cursor[2 * BQ * GS3];          // scatter cursors
__device__ int    g_cellid[2 * BQ * NPTS];         // cell id per point
__device__ float4 g_sorted[2 * BQ * NPTS];         // bucketed (x,y,z,orig_idx)
__device__ unsigned long long g_best_x[BQ * NPTS]; // (dist_bits<<32)|argmin_j
__device__ unsigned long long g_best_y[BQ * NPTS]; // (dist_bits<<32)|argmin_i
__device__ int    g_grid[BQ * GQ * GQ];            // ((n+1)<<1)|label, 0 = empty (re-zeroed by loss)
__device__ int    g_oflow [2 * BQ * NPTS];         // tier-2 query list
__device__ int    g_oflow2[2 * BQ * NPTS];         // tier-3 query list
__device__ int    g_ocount, g_ocount2;             // list sizes (re-zeroed by epilogue)
__device__ double g_sum;
__device__ int    g_vcnt;
__device__ unsigned g_done;

__device__ __forceinline__ int cell_coord(float v) {
    int c = (int)((v + 34.0f) * INVCELL);
    return min(max(c, 0), GS - 1);
}

// ===== histogram =====
__global__ void hist_kernel(const float* __restrict__ p_i,
                            const float* __restrict__ p_j) {
    int t = blockIdx.x * blockDim.x + threadIdx.x;   // [src][b][n]
    int n = t & (NPTS - 1), b = (t >> 13) & 1, src = t >> 14;
    const float* P = (src ? p_j : p_i) + ((size_t)b * NPTS + n) * 3;
    int cell = (cell_coord(P[2]) * GS + cell_coord(P[1])) * GS + cell_coord(P[0]);
    g_cellid[t] = cell;
    atomicAdd(&g_ccnt[(src * BQ + b) * GS3 + cell], 1);
}

// ===== exclusive scan per combo; offs+sentinel, cursors; re-zero counts =====
__global__ void scan_kernel() {
    const int combo = blockIdx.x;
    const int base  = combo * GS3;
    const int obase = combo * (GS3 + 1);
    const int lane = threadIdx.x & 31, warp = threadIdx.x >> 5;
    __shared__ int wsum[16];

    int v[8]; int s = 0;
    #pragma unroll
    for (int k = 0; k < 8; k++) { v[k] = g_ccnt[base + threadIdx.x * 8 + k]; s += v[k]; }

    int inc = s;
    #pragma unroll
    for (int o = 1; o < 32; o <<= 1) {
        int x = __shfl_up_sync(0xFFFFFFFFu, inc, o);
        if (lane >= o) inc += x;
    }
    if (lane == 31) wsum[warp] = inc;
    __syncthreads();
    if (warp == 0 && lane < 16) {
        int w = wsum[lane];
        #pragma unroll
        for (int o = 1; o < 16; o <<= 1) {
            int x = __shfl_up_sync(0xFFFFu, w, o);
            if (lane >= o) w += x;
        }
        wsum[lane] = w;
    }
    __syncthreads();
    int excl = inc - s + (warp ? wsum[warp - 1] : 0);
    #pragma unroll
    for (int k = 0; k < 8; k++) {
        int idx = threadIdx.x * 8 + k;
        g_offs[obase + idx] = excl;
        g_cursor[base + idx] = excl;
        g_ccnt[base + idx] = 0;          // restore for next replay
        excl += v[k];
    }
    if (threadIdx.x == 0) g_offs[obase + GS3] = NPTS;
}

// ===== scatter points into bucket order =====
__global__ void scatter_kernel(const float* __restrict__ p_i,
                               const float* __restrict__ p_j) {
    int t = blockIdx.x * blockDim.x + threadIdx.x;
    int n = t & (NPTS - 1), b = (t >> 13) & 1, src = t >> 14;
    const float* P = (src ? p_j : p_i) + ((size_t)b * NPTS + n) * 3;
    int cell = g_cellid[t];
    int pos = atomicAdd(&g_cursor[(src * BQ + b) * GS3 + cell], 1);
    g_sorted[(src * BQ + b) * NPTS + pos] = make_float4(P[0], P[1], P[2], __int_as_float(n));
}

__device__ __forceinline__ void eval_range(const float4* __restrict__ T,
                                           int p0, int p1,
                                           float qx, float qy, float qz,
                                           unsigned long long& bestkey) {
    #pragma unroll 2
    for (int p = p0; p < p1; p++) {
        float4 tp = T[p];
        // same fp32 op order as the reference: (|dx|+|dy|)+|dz|
        float d = fabsf(qx - tp.x) + fabsf(qy - tp.y);
        d += fabsf(qz - tp.z);
        unsigned long long key =
            ((unsigned long long)__float_as_uint(d) << 32) |
            (unsigned)__float_as_int(tp.w);
        if (key < bestkey) bestkey = key;
    }
}

// ===== tier 1: 3x3x3 cell box, 2 lanes/query (measured 13.3us) =====
// Rows split by parity across the lane pair; row x-runs are contiguous offs
// ranges, all prefetched up-front. Packed (dist_bits<<32)|orig key-min = exact
// min dist, min-index tie-break (jnp.argmin). If best could still lose to a
// Chebyshev>=2 candidate (L1 lower bound CELLSZ), push query to tier 2.
__global__ void query_kernel() {
    int t = blockIdx.x * blockDim.x + threadIdx.x;
    const int sub = t & 1;
    int g = t >> 1;                                  // [dir][b][q]
    int q = g & (NPTS - 1), b = (g >> 13) & 1, dir = g >> 14;
    int qc = dir * BQ + b;
    int tc = (1 - dir) * BQ + b;
    const unsigned gmask = 0x3u << (threadIdx.x & 30);

    float4 Q = g_sorted[qc * NPTS + q];
    const float qx = Q.x, qy = Q.y, qz = Q.z;
    const int orig = __float_as_int(Q.w);

    const int* __restrict__ offs = &g_offs[tc * (GS3 + 1)];
    const float4* __restrict__ T = &g_sorted[tc * NPTS];

    const int qcx = cell_coord(qx), qcy = cell_coord(qy), qcz = cell_coord(qz);
    const int x0 = max(qcx - 1, 0), x1 = min(qcx + 1, GS - 1);

    int P0[9], P1[9];
    #pragma unroll
    for (int k = 0; k < 9; k++) {
        int dz = k / 3 - 1, dy = k - (k / 3) * 3 - 1;
        int cz = qcz + dz, cy = qcy + dy;
        bool mine = ((k & 1) == sub) & (cz >= 0) & (cz < GS) & (cy >= 0) & (cy < GS);
        int rowbase = (cz * GS + cy) * GS;
        P0[k] = mine ? __ldg(&offs[rowbase + x0])     : 0;
        P1[k] = mine ? __ldg(&offs[rowbase + x1 + 1]) : 0;
    }

    unsigned long long bestkey = ((unsigned long long)0x7F800000u << 32); // +inf
    #pragma unroll
    for (int k = 0; k < 9; k++)
        eval_range(T, P0[k], P1[k], qx, qy, qz, bestkey);

    {
        unsigned long long other = __shfl_xor_sync(gmask, bestkey, 1);
        if (other < bestkey) bestkey = other;
    }

    if (sub == 0) {
        (dir ? g_best_y : g_best_x)[b * NPTS + orig] = bestkey;
        float bestd = __uint_as_float((unsigned)(bestkey >> 32));
        if (!(CELLSZ - 1e-3f > bestd)) {
            int e = atomicAdd(&g_ocount, 1);
            g_oflow[e] = g;
        }
    }
}

// ===== tier 2: warp per overflow query (grid-stride), 5x5x5 box =====
// 25 rows, one per lane (lanes 25-31 idle but hold a valid key for the
// reduce). Warp-uniform control flow, full-warp shfl reduce, bounded grid.
// Redundantly re-covers the 3x3x3 box (key-min idempotent). Anything still
// uncovered is at Chebyshev>=3 ==> L1 >= 2*CELLSZ; escalate only then.
__global__ void oflow2_kernel() {
    const int lane = threadIdx.x & 31;
    const int nw   = (gridDim.x * blockDim.x) >> 5;
    const int w0   = (blockIdx.x * blockDim.x + threadIdx.x) >> 5;
    const int cnt  = g_ocount;

    for (int e = w0; e < cnt; e += nw) {
        int g = g_oflow[e];
        int q = g & (NPTS - 1), b = (g >> 13) & 1, dir = g >> 14;
        int qc = dir * BQ + b, tc = (1 - dir) * BQ + b;

        float4 Q = g_sorted[qc * NPTS + q];
        const float qx = Q.x, qy = Q.y, qz = Q.z;
        const int orig = __float_as_int(Q.w);

        const int* __restrict__ offs = &g_offs[tc * (GS3 + 1)];
        const float4* __restrict__ T = &g_sorted[tc * NPTS];

        const int qcx = cell_coord(qx), qcy = cell_coord(qy), qcz = cell_coord(qz);
        const int x0 = max(qcx - 2, 0), x1 = min(qcx + 2, GS - 1);

        unsigned long long bestkey = (dir ? g_best_y : g_best_x)[b * NPTS + orig];

        if (lane < 25) {
            int cz = qcz + lane / 5 - 2;
            int cy = qcy + lane % 5 - 2;
            if (cz >= 0 && cz < GS && cy >= 0 && cy < GS) {
                int rowbase = (cz * GS + cy) * GS;
                eval_range(T, offs[rowbase + x0], offs[rowbase + x1 + 1],
                           qx, qy, qz, bestkey);
            }
        }
        #pragma unroll
        for (int o = 1; o <= 16; o <<= 1) {
            unsigned long long other = __shfl_xor_sync(0xFFFFFFFFu, bestkey, o);
            if (other < bestkey) bestkey = other;
        }

        if (lane == 0) {
            (dir ? g_best_y : g_best_x)[b * NPTS + orig] = bestkey;
            float bestd = __uint_as_float((unsigned)(bestkey >> 32));
            if (!(2.0f * CELLSZ - 1e-3f > bestd)) {
                int e2 = atomicAdd(&g_ocount2, 1);
                g_oflow2[e2] = g;
            }
        }
    }
}

// ===== tier 3 (corner pathologies only): rings r>=3, warp/query, grid-stride =====
__global__ void oflow3_kernel() {
    const int lane = threadIdx.x & 31;
    const int nw   = (gridDim.x * blockDim.x) >> 5;
    const int w0   = (blockIdx.x * blockDim.x + threadIdx.x) >> 5;
    const int cnt  = g_ocount2;

    for (int e = w0; e < cnt; e += nw) {
        int g = g_oflow2[e];
        int q = g & (NPTS - 1), b = (g >> 13) & 1, dir = g >> 14;
        int qc = dir * BQ + b, tc = (1 - dir) * BQ + b;

        float4 Q = g_sorted[qc * NPTS + q];
        const float qx = Q.x, qy = Q.y, qz = Q.z;
        const int orig = __float_as_int(Q.w);

        const int* __restrict__ offs = &g_offs[tc * (GS3 + 1)];
        const float4* __restrict__ T = &g_sorted[tc * NPTS];

        const int qcx = cell_coord(qx), qcy = cell_coord(qy), qcz = cell_coord(qz);

        unsigned long long bestkey = (dir ? g_best_y : g_best_x)[b * NPTS + orig];

        for (int r = 3; r < GS; r++) {
            float bestd = __uint_as_float((unsigned)(bestkey >> 32));
            if ((float)(r - 1) * CELLSZ - 1e-3f > bestd) break;

            int z0 = max(qcz - r, 0), z1 = min(qcz + r, GS - 1);
            int y0 = max(qcy - r, 0), y1 = min(qcy + r, GS - 1);
            int x0 = max(qcx - r, 0), x1 = min(qcx + r, GS - 1);
            int k = 0;
            for (int cz = z0; cz <= z1; cz++) {
                int az = abs(cz - qcz);
                for (int cy = y0; cy <= y1; cy++) {
                    if ((k++ & 31) != lane) continue;
                    int am = max(az, abs(cy - qcy));
                    int rowbase = (cz * GS + cy) * GS;
                    if (am == r) {
                        eval_range(T, offs[rowbase + x0], offs[rowbase + x1 + 1],
                                   qx, qy, qz, bestkey);
                    } else {
                        #pragma unroll
                        for (int sgn = 0; sgn < 2; sgn++) {
                            int cx = sgn ? qcx + r : qcx - r;
                            if (cx < 0 || cx > GS - 1) continue;
                            int c = rowbase + cx;
                            eval_range(T, offs[c], offs[c + 1], qx, qy, qz, bestkey);
                        }
                    }
                }
            }
            #pragma unroll
            for (int o = 1; o <= 16; o <<= 1) {
                unsigned long long other = __shfl_xor_sync(0xFFFFFFFFu, bestkey, o);
                if (other < bestkey) bestkey = other;
            }
        }

        if (lane == 0)
            (dir ? g_best_y : g_best_x)[b * NPTS + orig] = bestkey;
    }
}

// ===== epilogue: classify, gather p_j, scatter label into grid =====
__global__ void epilogue_kernel(const float* __restrict__ pj,
                                const float* __restrict__ flow_err,
                                const int*  __restrict__ nf) {
    int t = blockIdx.x * blockDim.x + threadIdx.x; // = b*NPTS + n
    int b = t >> 13;
    int n = t & (NPTS - 1);
    if (t == 0) { g_ocount = 0; g_ocount2 = 0; }   // restore for next replay

    float fe = __ldg(&flow_err[t]);
    int   nfv = __ldg(&nf[t]);
    unsigned long long kx = g_best_x[t];
    unsigned long long ky = g_best_y[t];

    float chx = __uint_as_float((unsigned)(kx >> 32));
    float chy = __uint_as_float((unsigned)(ky >> 32));
    int   jr  = (int)(kx & 0xFFFFFFFFu);

    float rigid = (chx + chy) * 0.5f;          // same op order as reference
    bool  dyn   = fe > rigid;
    int   idx   = dyn ? nfv : jr;
    int   label = dyn ? 1 : 0;

    const float* P = pj + ((size_t)b * NPTS + idx) * 3;
    float px = P[0], py = P[1];

    // IEEE fp32 divide to match XLA exactly (immune to --use_fast_math)
    int gx = (int)__fdiv_rn(px - XMINF, CELLW);
    int gy = (int)__fdiv_rn(py - XMINF, CELLW);
    gx = min(max(gx, 0), GQ - 1);
    gy = min(max(gy, 0), GQ - 1);

    atomicMax(&g_grid[(b * GQ + gx) * GQ + gy], ((n + 1) << 1) | label);
}

// ===== masked cross-entropy + fused finalize (last-block pattern) =====
__global__ void loss_kernel(const float* __restrict__ mos, float* __restrict__ out) {
    int t = blockIdx.x * blockDim.x + threadIdx.x;
    float s = 0.0f;
    int   c = 0;
    {
        int v = g_grid[t];
        if (v > 0) {
            g_grid[t] = 0;                       // restore for next replay
            int label = v & 1;
            int b     = t >> 16;
            int cell  = t & (GQ * GQ - 1);
            const float* Mb = mos + (size_t)b * 2 * GQ * GQ;
            float m0 = Mb[cell];
            float m1 = Mb[GQ * GQ + cell];
            float lse = fmaxf(m0, m1) + log1pf(__expf(-fabsf(m0 - m1)));
            s = lse - (label ? m1 : m0);
            c = 1;
        }
    }
    #pragma unroll
    for (int o = 16; o > 0; o >>= 1) {
        s += __shfl_down_sync(0xFFFFFFFFu, s, o);
        c += __shfl_down_sync(0xFFFFFFFFu, c, o);
    }
    __shared__ float ss[8];
    __shared__ int   sc[8];
    __shared__ bool  sLast;
    int lane = threadIdx.x & 31, warp = threadIdx.x >> 5;
    if (lane == 0) { ss[warp] = s; sc[warp] = c; }
    __syncthreads();
    if (warp == 0) {
        s = (lane < 8) ? ss[lane] : 0.0f;
        c = (lane < 8) ? sc[lane] : 0;
        #pragma unroll
        for (int o = 4; o > 0; o >>= 1) {
            s += __shfl_down_sync(0xFFFFFFFFu, s, o);
            c += __shfl_down_sync(0xFFFFFFFFu, c, o);
        }
        if (lane == 0) {
            if (s != 0.0f) atomicAdd(&g_sum, (double)s);
            if (c)         atomicAdd(&g_vcnt, c);
            __threadfence();
            unsigned d = atomicAdd(&g_done, 1u);
            sLast = (d == gridDim.x - 1);
        }
    }
    __syncthreads();
    if (sLast && threadIdx.x == 0) {
        int cnt = g_vcnt;
        if (cnt < 1) cnt = 1;
        out[0] = (float)(g_sum / (double)cnt);
        g_sum = 0.0; g_vcnt = 0; g_done = 0;
    }
}

// -------- launch: 8 graph nodes, all bounded grids --------
extern "C" void kernel_launch(void* const* d_in, const int* in_sizes, int n_in,
                              void* d_out, int out_size) {
    const float* p_i  = (const float*)d_in[0]; // (B,N,3)
    const float* mos  = (const float*)d_in[1]; // (B,2,G,G)
    const float* p_j  = (const float*)d_in[2]; // (B,M,3)
    const float* ferr = (const float*)d_in[3]; // (B,N)
    const int*   nf   = (const int*)d_in[4];   // (B,N,1)
    float* out = (float*)d_out;

    hist_kernel<<<(2 * BQ * NPTS) / 256, 256>>>(p_i, p_j);
    scan_kernel<<<2 * BQ, 512>>>();
    scatter_kernel<<<(2 * BQ * NPTS) / 256, 256>>>(p_i, p_j);
    query_kernel<<<(2 * BQ * NPTS * 2) / 256, 256>>>();
    oflow2_kernel<<<148, 256>>>();   // grid-stride over overflow list
    oflow3_kernel<<<24, 256>>>();    // grid-stride; ~empty
    epilogue_kernel<<<(BQ * NPTS) / 256, 256>>>(p_j, ferr, nf);
    loss_kernel<<<(BQ * GQ * GQ) / 256, 256>>>(mos, out);
}

// round 10
// speedup vs baseline: 4.4244x; 1.1228x over previous
#include <cuda_runtime.h>
#include <cuda_bf16.h>

// Problem constants (fixed by the reference)
#define BQ    2
#define NPTS  8192
#define GQ    256
#define XMINF (-35.0f)
#define CELLW (0.2734375f)   // 70/256, exactly representable

// Spatial bucket grid for exact 1-NN
#define GS      16
#define GS3     (GS * GS * GS)
#define CELLSZ  4.25f          // 68/16, exact in fp32
#define INVCELL (1.0f / 4.25f)

// -------- scratch (device globals; zero-initialized at load; every kernel
// restores what it consumed, so graph replays see identical entry state) ----
__device__ int    g_ccnt  [2 * BQ * GS3];          // per-cell counts (re-zeroed by scan)
__device__ int    g_offs  [2 * BQ * (GS3 + 1)];    // exclusive offsets + sentinel
__device__ int    g_cursor[2 * BQ * GS3];          // scatter cursors
__device__ int    g_cellid[2 * BQ * NPTS];         // cell id per point
__device__ float4 g_sorted[2 * BQ * NPTS];         // bucketed (x,y,z,orig_idx)
__device__ unsigned long long g_best_x[BQ * NPTS]; // (dist_bits<<32)|argmin_j
__device__ unsigned long long g_best_y[BQ * NPTS]; // (dist_bits<<32)|argmin_i
__device__ int    g_grid[BQ * GQ * GQ];            // ((n+1)<<1)|label, 0 = empty (re-zeroed by loss)
__device__ int    g_oflow[2 * BQ * NPTS];          // overflow query list
__device__ int    g_ocount;                        // list size (re-zeroed by epilogue)
__device__ double g_sum;
__device__ int    g_vcnt;
__device__ unsigned g_done;

__device__ __forceinline__ int cell_coord(float v) {
    int c = (int)((v + 34.0f) * INVCELL);
    return min(max(c, 0), GS - 1);
}

// ===== histogram =====
__global__ void hist_kernel(const float* __restrict__ p_i,
                            const float* __restrict__ p_j) {
    int t = blockIdx.x * blockDim.x + threadIdx.x;   // [src][b][n]
    int n = t & (NPTS - 1), b = (t >> 13) & 1, src = t >> 14;
    const float* P = (src ? p_j : p_i) + ((size_t)b * NPTS + n) * 3;
    int cell = (cell_coord(P[2]) * GS + cell_coord(P[1])) * GS + cell_coord(P[0]);
    g_cellid[t] = cell;
    atomicAdd(&g_ccnt[(src * BQ + b) * GS3 + cell], 1);
}

// ===== exclusive scan per combo; offs+sentinel, cursors; re-zero counts =====
__global__ void scan_kernel() {
    const int combo = blockIdx.x;
    const int base  = combo * GS3;
    const int obase = combo * (GS3 + 1);
    const int lane = threadIdx.x & 31, warp = threadIdx.x >> 5;
    __shared__ int wsum[16];

    int v[8]; int s = 0;
    #pragma unroll
    for (int k = 0; k < 8; k++) { v[k] = g_ccnt[base + threadIdx.x * 8 + k]; s += v[k]; }

    int inc = s;
    #pragma unroll
    for (int o = 1; o < 32; o <<= 1) {
        int x = __shfl_up_sync(0xFFFFFFFFu, inc, o);
        if (lane >= o) inc += x;
    }
    if (lane == 31) wsum[warp] = inc;
    __syncthreads();
    if (warp == 0 && lane < 16) {
        int w = wsum[lane];
        #pragma unroll
        for (int o = 1; o < 16; o <<= 1) {
            int x = __shfl_up_sync(0xFFFFu, w, o);
            if (lane >= o) w += x;
        }
        wsum[lane] = w;
    }
    __syncthreads();
    int excl = inc - s + (warp ? wsum[warp - 1] : 0);
    #pragma unroll
    for (int k = 0; k < 8; k++) {
        int idx = threadIdx.x * 8 + k;
        g_offs[obase + idx] = excl;
        g_cursor[base + idx] = excl;
        g_ccnt[base + idx] = 0;          // restore for next replay
        excl += v[k];
    }
    if (threadIdx.x == 0) g_offs[obase + GS3] = NPTS;
}

// ===== scatter points into bucket order =====
__global__ void scatter_kernel(const float* __restrict__ p_i,
                               const float* __restrict__ p_j) {
    int t = blockIdx.x * blockDim.x + threadIdx.x;
    int n = t & (NPTS - 1), b = (t >> 13) & 1, src = t >> 14;
    const float* P = (src ? p_j : p_i) + ((size_t)b * NPTS + n) * 3;
    int cell = g_cellid[t];
    int pos = atomicAdd(&g_cursor[(src * BQ + b) * GS3 + cell], 1);
    g_sorted[(src * BQ + b) * NPTS + pos] = make_float4(P[0], P[1], P[2], __int_as_float(n));
}

__device__ __forceinline__ void eval_range(const float4* __restrict__ T,
                                           int p0, int p1,
                                           float qx, float qy, float qz,
                                           unsigned long long& bestkey) {
    #pragma unroll 2
    for (int p = p0; p < p1; p++) {
        float4 tp = T[p];
        // same fp32 op order as the reference: (|dx|+|dy|)+|dz|
        float d = fabsf(qx - tp.x) + fabsf(qy - tp.y);
        d += fabsf(qz - tp.z);
        unsigned long long key =
            ((unsigned long long)__float_as_uint(d) << 32) |
            (unsigned)__float_as_int(tp.w);
        if (key < bestkey) bestkey = key;
    }
}

// ===== tier 1: 3x3x3 cell box, 4 lanes/query =====
// The 9 candidate rows are split round-robin (k&3) across the aligned 4-lane
// group (<=3 rows/lane, all prefetched up-front). No loops with data-dependent
// trip counts -> no divergence serialization. Packed (dist_bits<<32)|orig
// key-min = exact min dist, min-index tie-break (jnp.argmin first occurrence).
// If best could still lose to a Chebyshev>=2 candidate (L1 lower bound
// CELLSZ), push the query to the overflow kernel.
__global__ void query_kernel() {
    int t = blockIdx.x * blockDim.x + threadIdx.x;
    const int sub = t & 3;
    int g = t >> 2;                                  // [dir][b][q]
    int q = g & (NPTS - 1), b = (g >> 13) & 1, dir = g >> 14;
    int qc = dir * BQ + b;
    int tc = (1 - dir) * BQ + b;
    const unsigned gmask = 0xFu << (threadIdx.x & 28);

    float4 Q = g_sorted[qc * NPTS + q];
    const float qx = Q.x, qy = Q.y, qz = Q.z;
    const int orig = __float_as_int(Q.w);

    const int* __restrict__ offs = &g_offs[tc * (GS3 + 1)];
    const float4* __restrict__ T = &g_sorted[tc * NPTS];

    const int qcx = cell_coord(qx), qcy = cell_coord(qy), qcz = cell_coord(qz);
    const int x0 = max(qcx - 1, 0), x1 = min(qcx + 1, GS - 1);

    // lane sub owns rows k = sub, sub+4, sub+8 (k<9); prefetch ranges (MLP)
    int P0[3], P1[3];
    #pragma unroll
    for (int kk = 0; kk < 3; kk++) {
        int k = sub + kk * 4;
        int dz = k / 3 - 1, dy = k - (k / 3) * 3 - 1;
        int cz = qcz + dz, cy = qcy + dy;
        bool mine = (k < 9) & (cz >= 0) & (cz < GS) & (cy >= 0) & (cy < GS);
        int rowbase = (cz * GS + cy) * GS;
        P0[kk] = mine ? __ldg(&offs[rowbase + x0])     : 0;
        P1[kk] = mine ? __ldg(&offs[rowbase + x1 + 1]) : 0;
    }

    unsigned long long bestkey = ((unsigned long long)0x7F800000u << 32); // +inf
    #pragma unroll
    for (int kk = 0; kk < 3; kk++)
        eval_range(T, P0[kk], P1[kk], qx, qy, qz, bestkey);

    #pragma unroll
    for (int o = 1; o <= 2; o <<= 1) {
        unsigned long long other = __shfl_xor_sync(gmask, bestkey, o);
        if (other < bestkey) bestkey = other;
    }

    if (sub == 0) {
        (dir ? g_best_y : g_best_x)[b * NPTS + orig] = bestkey;
        float bestd = __uint_as_float((unsigned)(bestkey >> 32));
        if (!(CELLSZ - 1e-3f > bestd)) {
            int e = atomicAdd(&g_ocount, 1);
            g_oflow[e] = g;
        }
    }
}

// ===== overflow: ONE query per warp, grid-stride list =====
// Stage A: 5x5x5 box, one row per lane (lanes 25-31 idle, valid keys for the
// reduce). Stage B (only if best >= 2*CELLSZ, i.e. a Chebyshev>=3 candidate
// could still win): expanding rings r>=3. One query per warp means every
// loop is warp-uniform -> no divergence serialization. Bounded grid, no
// empty-block waves. Termination bound (r-1)*CELLSZ is a strict L1 lower
// bound with margin; ties can never be skipped.
__global__ void oflow_kernel() {
    const int lane = threadIdx.x & 31;
    const int nw   = (gridDim.x * blockDim.x) >> 5;
    const int w0   = (blockIdx.x * blockDim.x + threadIdx.x) >> 5;
    const int cnt  = g_ocount;

    for (int e = w0; e < cnt; e += nw) {
        int g = g_oflow[e];
        int q = g & (NPTS - 1), b = (g >> 13) & 1, dir = g >> 14;
        int qc = dir * BQ + b, tc = (1 - dir) * BQ + b;

        float4 Q = g_sorted[qc * NPTS + q];
        const float qx = Q.x, qy = Q.y, qz = Q.z;
        const int orig = __float_as_int(Q.w);

        const int* __restrict__ offs = &g_offs[tc * (GS3 + 1)];
        const float4* __restrict__ T = &g_sorted[tc * NPTS];

        const int qcx = cell_coord(qx), qcy = cell_coord(qy), qcz = cell_coord(qz);

        unsigned long long bestkey = (dir ? g_best_y : g_best_x)[b * NPTS + orig];

        // ---- stage A: 5x5x5 box, one row per lane ----
        {
            const int x0 = max(qcx - 2, 0), x1 = min(qcx + 2, GS - 1);
            if (lane < 25) {
                int cz = qcz + lane / 5 - 2;
                int cy = qcy + lane % 5 - 2;
                if (cz >= 0 && cz < GS && cy >= 0 && cy < GS) {
                    int rowbase = (cz * GS + cy) * GS;
                    eval_range(T, offs[rowbase + x0], offs[rowbase + x1 + 1],
                               qx, qy, qz, bestkey);
                }
            }
            #pragma unroll
            for (int o = 1; o <= 16; o <<= 1) {
                unsigned long long other = __shfl_xor_sync(0xFFFFFFFFu, bestkey, o);
                if (other < bestkey) bestkey = other;
            }
        }

        // ---- stage B: rings r>=3 (anything uncovered has L1 >= 2*CELLSZ) ----
        for (int r = 3; r < GS; r++) {
            float bestd = __uint_as_float((unsigned)(bestkey >> 32));
            if ((float)(r - 1) * CELLSZ - 1e-3f > bestd) break;

            int z0 = max(qcz - r, 0), z1 = min(qcz + r, GS - 1);
            int y0 = max(qcy - r, 0), y1 = min(qcy + r, GS - 1);
            int x0 = max(qcx - r, 0), x1 = min(qcx + r, GS - 1);
            int k = 0;
            for (int cz = z0; cz <= z1; cz++) {
                int az = abs(cz - qcz);
                for (int cy = y0; cy <= y1; cy++) {
                    if ((k++ & 31) != lane) continue;
                    int am = max(az, abs(cy - qcy));
                    int rowbase = (cz * GS + cy) * GS;
                    if (am == r) {
                        eval_range(T, offs[rowbase + x0], offs[rowbase + x1 + 1],
                                   qx, qy, qz, bestkey);
                    } else {
                        #pragma unroll
                        for (int sgn = 0; sgn < 2; sgn++) {
                            int cx = sgn ? qcx + r : qcx - r;
                            if (cx < 0 || cx > GS - 1) continue;
                            int c = rowbase + cx;
                            eval_range(T, offs[c], offs[c + 1], qx, qy, qz, bestkey);
                        }
                    }
                }
            }
            #pragma unroll
            for (int o = 1; o <= 16; o <<= 1) {
                unsigned long long other = __shfl_xor_sync(0xFFFFFFFFu, bestkey, o);
                if (other < bestkey) bestkey = other;
            }
        }

        if (lane == 0)
            (dir ? g_best_y : g_best_x)[b * NPTS + orig] = bestkey;
    }
}

// ===== epilogue: classify, gather p_j, scatter label into grid =====
// Last-write-wins via atomicMax on ((n+1)<<1)|label (0 = empty cell).
__global__ void epilogue_kernel(const float* __restrict__ pj,
                                const float* __restrict__ flow_err,
                                const int*  __restrict__ nf) {
    int t = blockIdx.x * blockDim.x + threadIdx.x; // = b*NPTS + n
    int b = t >> 13;
    int n = t & (NPTS - 1);
    if (t == 0) g_ocount = 0;            // restore for next replay

    float fe = __ldg(&flow_err[t]);
    int   nfv = __ldg(&nf[t]);
    unsigned long long kx = g_best_x[t];
    unsigned long long ky = g_best_y[t];

    float chx = __uint_as_float((unsigned)(kx >> 32));
    float chy = __uint_as_float((unsigned)(ky >> 32));
    int   jr  = (int)(kx & 0xFFFFFFFFu);

    float rigid = (chx + chy) * 0.5f;          // same op order as reference
    bool  dyn   = fe > rigid;
    int   idx   = dyn ? nfv : jr;
    int   label = dyn ? 1 : 0;

    const float* P = pj + ((size_t)b * NPTS + idx) * 3;
    float px = P[0], py = P[1];

    // IEEE fp32 divide to match XLA exactly (immune to --use_fast_math)
    int gx = (int)__fdiv_rn(px - XMINF, CELLW);
    int gy = (int)__fdiv_rn(py - XMINF, CELLW);
    gx = min(max(gx, 0), GQ - 1);
    gy = min(max(gy, 0), GQ - 1);

    atomicMax(&g_grid[(b * GQ + gx) * GQ + gy], ((n + 1) << 1) | label);
}

// ===== masked cross-entropy + fused finalize (last-block pattern) =====
__global__ void loss_kernel(const float* __restrict__ mos, float* __restrict__ out) {
    int t = blockIdx.x * blockDim.x + threadIdx.x;
    float s = 0.0f;
    int   c = 0;
    {
        int v = g_grid[t];
        if (v > 0) {
            g_grid[t] = 0;                       // restore for next replay
            int label = v & 1;
            int b     = t >> 16;
            int cell  = t & (GQ * GQ - 1);
            const float* Mb = mos + (size_t)b * 2 * GQ * GQ;
            float m0 = Mb[cell];
            float m1 = Mb[GQ * GQ + cell];
            float lse = fmaxf(m0, m1) + log1pf(__expf(-fabsf(m0 - m1)));
            s = lse - (label ? m1 : m0);
            c = 1;
        }
    }
    #pragma unroll
    for (int o = 16; o > 0; o >>= 1) {
        s += __shfl_down_sync(0xFFFFFFFFu, s, o);
        c += __shfl_down_sync(0xFFFFFFFFu, c, o);
    }
    __shared__ float ss[8];
    __shared__ int   sc[8];
    __shared__ bool  sLast;
    int lane = threadIdx.x & 31, warp = threadIdx.x >> 5;
    if (lane == 0) { ss[warp] = s; sc[warp] = c; }
    __syncthreads();
    if (warp == 0) {
        s = (lane < 8) ? ss[lane] : 0.0f;
        c = (lane < 8) ? sc[lane] : 0;
        #pragma unroll
        for (int o = 4; o > 0; o >>= 1) {
            s += __shfl_down_sync(0xFFFFFFFFu, s, o);
            c += __shfl_down_sync(0xFFFFFFFFu, c, o);
        }
        if (lane == 0) {
            if (s != 0.0f) atomicAdd(&g_sum, (double)s);
            if (c)         atomicAdd(&g_vcnt, c);
            __threadfence();
            unsigned d = atomicAdd(&g_done, 1u);
            sLast = (d == gridDim.x - 1);
        }
    }
    __syncthreads();
    if (sLast && threadIdx.x == 0) {
        int cnt = g_vcnt;
        if (cnt < 1) cnt = 1;
        out[0] = (float)(g_sum / (double)cnt);
        g_sum = 0.0; g_vcnt = 0; g_done = 0;
    }
}

// -------- launch: 7 graph nodes, all bounded grids --------
extern "C" void kernel_launch(void* const* d_in, const int* in_sizes, int n_in,
                              void* d_out, int out_size) {
    const float* p_i  = (const float*)d_in[0]; // (B,N,3)
    const float* mos  = (const float*)d_in[1]; // (B,2,G,G)
    const float* p_j  = (const float*)d_in[2]; // (B,M,3)
    const float* ferr = (const float*)d_in[3]; // (B,N)
    const int*   nf   = (const int*)d_in[4];   // (B,N,1)
    float* out = (float*)d_out;

    hist_kernel<<<(2 * BQ * NPTS) / 256, 256>>>(p_i, p_j);
    scan_kernel<<<2 * BQ, 512>>>();
    scatter_kernel<<<(2 * BQ * NPTS) / 256, 256>>>(p_i, p_j);
    query_kernel<<<(2 * BQ * NPTS * 4) / 256, 256>>>();
    oflow_kernel<<<148, 256>>>();    // grid-stride over overflow list
    epilogue_kernel<<<(BQ * NPTS) / 256, 256>>>(p_j, ferr, nf);
    loss_kernel<<<(BQ * GQ * GQ) / 256, 256>>>(mos, out);
}